// round 8
// baseline (speedup 1.0000x reference)
#include <cuda_runtime.h>
#include <cuda_bf16.h>
#include <cstdint>

// Problem constants
#define D_    256
#define HW_   1024            // 32*32
#define N_TOT 16384           // 16 * 1024 vectors
#define K_TOT 8192            // codebook entries
#define ZQ_ELEMS 4194304      // 16*256*32*32
#define NTILES 64             // K_TOT / 128 codes per tile
#define SLACK  6e-4f          // compaction threshold above approx min
#define MAXC   16             // max candidates per vector after compaction

// fp8 scaling: z * 16, codebook * 4096  ->  acc = 65536 * dot (exact pow2)
#define ACC_COEF  (-32.0f / 65536.0f)   // -4.8828125e-4f, exact

// ---- device scratch (no allocations allowed) ----
__device__ float g_cbnorm[K_TOT];
__device__ float g_znorm[N_TOT];
__device__ int   g_idx[N_TOT];
__device__ float g_partial[ZQ_ELEMS / 256];
__device__ __align__(16) uint8_t g_zf8[N_TOT * D_];   // [n][d] e4m3 (256B rows)
__device__ __align__(16) uint8_t g_cbf8[K_TOT * D_];  // [k][d] e4m3 (256B rows)
__device__ int   g_cand[N_TOT * MAXC];           // compacted candidates
__device__ int   g_candcnt[N_TOT];               // candidate counts

// ---- smem layout for the MMA kernel (dynamic) ----
#define SM_A   0               // 128 rows x 256B (z tile, resident)
#define SM_B   32768           // 2 x 128 rows x 256B (codebook, dbl buf)
#define SM_NK  98304           // 2 x 128 floats (code norms, dbl buf)
#define SM_TOTAL 100352        // also >= 96KB candidate table reuse

// ---- PTX helpers (non-'a' target instructions only) ----
__device__ __forceinline__ uint32_t smem_u32(const void* p) {
    uint32_t a;
    asm("{ .reg .u64 t; cvta.to.shared.u64 t, %1; cvt.u32.u64 %0, t; }"
        : "=r"(a) : "l"(p));
    return a;
}
__device__ __forceinline__ void cp_async16(uint32_t dst, const void* src) {
    asm volatile("cp.async.cg.shared.global [%0], [%1], 16;"
                 :: "r"(dst), "l"(src) : "memory");
}
#define CP_COMMIT() asm volatile("cp.async.commit_group;" ::: "memory")
#define CP_WAIT1()  asm volatile("cp.async.wait_group 1;" ::: "memory")
#define CP_WAIT0()  asm volatile("cp.async.wait_group 0;" ::: "memory")

#define LDSM4(r0, r1, r2, r3, addr)                                        \
    asm volatile("ldmatrix.sync.aligned.m8n8.x4.shared.b16 "               \
                 "{%0,%1,%2,%3}, [%4];"                                    \
                 : "=r"(r0), "=r"(r1), "=r"(r2), "=r"(r3) : "r"(addr))

// fp8 e4m3 MMA: m16n8k32, A row-major (k-contig), B col-major
#define MMAF8(d, a, b0, b1)                                                \
    asm volatile("mma.sync.aligned.m16n8k32.row.col.f32.e4m3.e4m3.f32 "    \
                 "{%0,%1,%2,%3}, {%4,%5,%6,%7}, {%8,%9}, {%0,%1,%2,%3};"   \
                 : "+f"((d)[0]), "+f"((d)[1]), "+f"((d)[2]), "+f"((d)[3])  \
                 : "r"((a)[0]), "r"((a)[1]), "r"((a)[2]), "r"((a)[3]),     \
                   "r"(b0), "r"(b1))

// pack two floats to e4m3x2 (lo -> low byte)
__device__ __forceinline__ uint16_t cvt_e4m3x2(float lo, float hi) {
    uint16_t r;
    asm("cvt.rn.satfinite.e4m3x2.f32 %0, %1, %2;" : "=h"(r) : "f"(hi), "f"(lo));
    return r;
}

// branchless top-3 min-chain update with a packed (score|local) u32
#define UPD3(CH, pval, loc) do {                                           \
    uint32_t _u = (__float_as_uint(pval) & 0xFFFFFF00u) | (loc);           \
    uint32_t _t1 = max(_u, (CH)[0]); (CH)[0] = min(_u, (CH)[0]);           \
    uint32_t _t2 = max(_t1, (CH)[1]); (CH)[1] = min(_t1, (CH)[1]);         \
    (CH)[2] = min(_t2, (CH)[2]);                                           \
} while (0)

// ============================================================
// prep: z squared norms per vector (launch #1)
// ============================================================
__global__ void znorm_kernel(const float* __restrict__ z) {
    int n = blockIdx.x * 256 + threadIdx.x;
    int b  = n >> 10;
    int hw = n & 1023;
    const float* p = z + (size_t)b * (D_ * HW_) + hw;
    double s = 0.0;
    #pragma unroll 8
    for (int c = 0; c < D_; c++) {
        float v = p[(size_t)c * HW_];
        s += (double)v * v;
    }
    g_znorm[n] = (float)s;
}

// ============================================================
// prep: fused codebook norms (fp64) + fp32 -> e4m3 (*4096) (launch #2)
// ============================================================
__global__ void cb_prep_kernel(const float* __restrict__ cb) {
    int warp = threadIdx.x >> 5;
    int lane = threadIdx.x & 31;
    int k = blockIdx.x * 8 + warp;
    const float4* row = (const float4*)(cb + (size_t)k * D_);
    float4 v0 = row[lane * 2];
    float4 v1 = row[lane * 2 + 1];
    double s = (double)v0.x * v0.x + (double)v0.y * v0.y
             + (double)v0.z * v0.z + (double)v0.w * v0.w
             + (double)v1.x * v1.x + (double)v1.y * v1.y
             + (double)v1.z * v1.z + (double)v1.w * v1.w;
    #pragma unroll
    for (int off = 16; off > 0; off >>= 1)
        s += __shfl_xor_sync(0xffffffffu, s, off);
    if (lane == 0) g_cbnorm[k] = (float)s;
    const float SC = 4096.f;
    uint32_t lo = (uint32_t)cvt_e4m3x2(v0.x * SC, v0.y * SC)
                | ((uint32_t)cvt_e4m3x2(v0.z * SC, v0.w * SC) << 16);
    uint32_t hi = (uint32_t)cvt_e4m3x2(v1.x * SC, v1.y * SC)
                | ((uint32_t)cvt_e4m3x2(v1.z * SC, v1.w * SC) << 16);
    uint2 o; o.x = lo; o.y = hi;
    *(uint2*)(g_cbf8 + (size_t)k * D_ + lane * 8) = o;
}

// ============================================================
// prep: z [b,c,hw] fp32 -> g_zf8 [n][c] e4m3 (*16, transpose) (launch #3)
// ============================================================
__global__ void cvt_z_kernel(const float* __restrict__ z) {
    __shared__ float t[32][33];
    int b  = blockIdx.z;
    int hw0 = blockIdx.y * 32;
    int c0  = blockIdx.x * 32;
    int tx = threadIdx.x, ty = threadIdx.y;   // 32 x 8
    #pragma unroll
    for (int r = 0; r < 4; r++) {
        int c = c0 + ty + r * 8;
        t[ty + r * 8][tx] = z[((size_t)b * D_ + c) * HW_ + hw0 + tx];
    }
    __syncthreads();
    // output: one u32 (4 e4m3) per thread, coalesced
    int tid = ty * 32 + tx;
    int u  = tid & 7;        // u32 index within the 32-c span
    int nl = tid >> 3;       // local n (0..31)
    const float SC = 16.f;
    float f0 = t[u * 4 + 0][nl] * SC;
    float f1 = t[u * 4 + 1][nl] * SC;
    float f2 = t[u * 4 + 2][nl] * SC;
    float f3 = t[u * 4 + 3][nl] * SC;
    uint32_t o = (uint32_t)cvt_e4m3x2(f0, f1)
               | ((uint32_t)cvt_e4m3x2(f2, f3) << 16);
    int n = b * HW_ + hw0 + nl;
    ((uint32_t*)g_zf8)[(size_t)n * 64 + blockIdx.x * 8 + u] = o;
}

// ============================================================
// main: e4m3 mma.sync candidate GEMM (launch #4 -> ncu profiles this).
// grid = 128 CTAs (128 z-rows each), 512 threads (16 warps, 4m x 4n).
// Warp tile 32(m) x 32(n); per thread 2 m16 x 4 n8 tiles, 32 accums.
// 8 k-steps of k=32. Epilogue: branchless packed-min top-3 per domain
// (32 domains/row), then threshold compaction (min + SLACK).
// ============================================================
__global__ __launch_bounds__(512, 1) void vq_mma_kernel() {
    extern __shared__ __align__(128) char smem[];
    const uint32_t sb = smem_u32(smem);
    const int tid  = threadIdx.x;
    const int lane = tid & 31;
    const int wid  = tid >> 5;
    const int wm   = wid & 3;      // warp row group (0..3), 32 rows each
    const int wn   = wid >> 2;     // warp col group (0..3), 32 cols each
    const int n0   = blockIdx.x * 128;

    // ---- load A (z rows): 2048 16B chunks, 4/thread, swizzled ----
    {
        const char* srcA = (const char*)g_zf8 + (size_t)n0 * 256;
        #pragma unroll
        for (int j = 0; j < 4; j++) {
            int i = tid + j * 512;
            int r = i >> 4, c16 = i & 15;
            uint32_t kb = c16 * 16;
            cp_async16(sb + SM_A + r * 256 + (kb ^ ((r & 7) << 4)),
                       srcA + (size_t)r * 256 + kb);
        }
    }
    // ---- load B tile 0 + norms ----
    {
        const char* srcB = (const char*)g_cbf8;
        #pragma unroll
        for (int j = 0; j < 4; j++) {
            int i = tid + j * 512;
            int r = i >> 4, c16 = i & 15;
            uint32_t kb = c16 * 16;
            cp_async16(sb + SM_B + r * 256 + (kb ^ ((r & 7) << 4)),
                       srcB + (size_t)r * 256 + kb);
        }
        if (tid < 32)
            cp_async16(sb + SM_NK + tid * 16, (const char*)g_cbnorm + tid * 16);
    }
    CP_COMMIT();

    // ldmatrix lane addressing (rows now 256B)
    const int lrow8 = ((lane >> 3) & 1) * 8 + (lane & 7);
    const uint32_t kext = (lane >> 4) * 16;
    const uint32_t xorv = (uint32_t)(lane & 7) << 4;
    uint32_t aBase[2];
    #pragma unroll
    for (int mt = 0; mt < 2; mt++)
        aBase[mt] = sb + SM_A + (wm * 32 + mt * 16 + lrow8) * 256;
    uint32_t bOff[2];
    #pragma unroll
    for (int np = 0; np < 2; np++)
        bOff[np] = (wn * 32 + np * 16 + lrow8) * 256;

    // packed top-3 chains: [ (mt*2+rowgroup)*2 + half ][3]
    uint32_t ch[8][3];
    #pragma unroll
    for (int l = 0; l < 8; l++)
        #pragma unroll
        for (int j = 0; j < 3; j++) ch[l][j] = 0xFFFFFFFFu;

    for (int t = 0; t < NTILES; t++) {
        const int buf = t & 1;
        if (t + 1 < NTILES) {
            const char* srcB = (const char*)g_cbf8 + (size_t)(t + 1) * 128 * 256;
            uint32_t dst = sb + SM_B + (buf ^ 1) * 32768;
            #pragma unroll
            for (int j = 0; j < 4; j++) {
                int i = tid + j * 512;
                int r = i >> 4, c16 = i & 15;
                uint32_t kb = c16 * 16;
                cp_async16(dst + r * 256 + (kb ^ ((r & 7) << 4)),
                           srcB + (size_t)r * 256 + kb);
            }
            if (tid < 32)
                cp_async16(sb + SM_NK + (buf ^ 1) * 512 + tid * 16,
                           (const char*)(g_cbnorm + (t + 1) * 128) + tid * 16);
            CP_COMMIT();
            CP_WAIT1();
        } else {
            CP_WAIT0();
        }
        __syncthreads();

        // ---- 8 k-steps of k32 fp8 mma over D=256 ----
        float acc[2][4][4];
        #pragma unroll
        for (int mt = 0; mt < 2; mt++)
            #pragma unroll
            for (int nt = 0; nt < 4; nt++)
                #pragma unroll
                for (int q = 0; q < 4; q++) acc[mt][nt][q] = 0.f;

        const uint32_t bBase = sb + SM_B + buf * 32768;
        #pragma unroll
        for (int ks = 0; ks < 8; ks++) {
            const uint32_t kb = ks * 32;
            uint32_t a[2][4];
            #pragma unroll
            for (int mt = 0; mt < 2; mt++)
                LDSM4(a[mt][0], a[mt][1], a[mt][2], a[mt][3],
                      aBase[mt] + ((kb + kext) ^ xorv));
            uint32_t b[2][4];
            #pragma unroll
            for (int np = 0; np < 2; np++)
                LDSM4(b[np][0], b[np][1], b[np][2], b[np][3],
                      bBase + bOff[np] + ((kb + kext) ^ xorv));
            #pragma unroll
            for (int mt = 0; mt < 2; mt++)
                #pragma unroll
                for (int nt = 0; nt < 4; nt++)
                    MMAF8(acc[mt][nt], a[mt],
                          b[nt >> 1][nt & 1], b[nt >> 1][2 + (nt & 1)]);
        }

        // ---- epilogue: packed branchless top-3 updates ----
        {
            const float* nk = (const float*)(smem + SM_NK + buf * 512);
            const int cb0 = wn * 32 + 2 * (lane & 3);
            const uint32_t tb4 = (uint32_t)t * 4;
            #pragma unroll
            for (int nt = 0; nt < 4; nt++) {
                int c = cb0 + nt * 8;
                float nkp0 = fmaf(nk[c],     16.f, 2.f);
                float nkp1 = fmaf(nk[c + 1], 16.f, 2.f);
                const int half = nt >> 1;
                const uint32_t loc0 = tb4 + (uint32_t)(nt & 1) * 2;
                const uint32_t loc1 = loc0 + 1;
                #pragma unroll
                for (int mt = 0; mt < 2; mt++) {
                    UPD3(ch[(mt * 2 + 0) * 2 + half],
                         fmaf(acc[mt][nt][0], ACC_COEF, nkp0), loc0);
                    UPD3(ch[(mt * 2 + 0) * 2 + half],
                         fmaf(acc[mt][nt][1], ACC_COEF, nkp1), loc1);
                    UPD3(ch[(mt * 2 + 1) * 2 + half],
                         fmaf(acc[mt][nt][2], ACC_COEF, nkp0), loc0);
                    UPD3(ch[(mt * 2 + 1) * 2 + half],
                         fmaf(acc[mt][nt][3], ACC_COEF, nkp1), loc1);
                }
            }
        }
        __syncthreads();   // safe to overwrite buf next iter
    }

    // ---- dump decoded (score, k) to smem table: [128 rows][32 dom][3] ----
    {
        uint32_t* tabS = (uint32_t*)smem;            // 48KB
        int*      tabK = (int*)(smem + 49152);       // 48KB
        const int colbase = wn * 32 + 2 * (lane & 3);
        #pragma unroll
        for (int mt = 0; mt < 2; mt++)
            #pragma unroll
            for (int rg = 0; rg < 2; rg++) {
                int r = wm * 32 + mt * 16 + rg * 8 + (lane >> 2);
                #pragma unroll
                for (int half = 0; half < 2; half++) {
                    int dom = wn * 4 + (lane & 3) + half * 16;
                    const uint32_t* c3 = ch[(mt * 2 + rg) * 2 + half];
                    #pragma unroll
                    for (int j = 0; j < 3; j++) {
                        uint32_t e = c3[j];
                        uint32_t loc = e & 255u;
                        int k = (int)(loc >> 2) * 128 + colbase + half * 16
                              + (int)((loc >> 1) & 1) * 8 + (int)(loc & 1);
                        tabS[r * 96 + dom * 3 + j] = e & 0xFFFFFF00u;
                        tabK[r * 96 + dom * 3 + j] = k;
                    }
                }
            }
    }
    __syncthreads();

    // ---- threshold compaction: one thread per row ----
    if (tid < 128) {
        const uint32_t* es = (const uint32_t*)smem + tid * 96;
        const int*      ek = (const int*)(smem + 49152) + tid * 96;
        uint32_t mn = es[0];
        #pragma unroll 8
        for (int i = 1; i < 96; i++) mn = min(mn, es[i]);
        float thr = __uint_as_float(mn) + SLACK * 16.f;   // packed scale
        int cnt = 0;
        int n = n0 + tid;
        #pragma unroll 8
        for (int i = 0; i < 96; i++) {
            if (__uint_as_float(es[i]) <= thr && cnt < MAXC)
                g_cand[n * MAXC + cnt++] = ek[i];
        }
        g_candcnt[n] = cnt;
    }
}

// ============================================================
// exact rescore, warp-cooperative over the compacted candidate
// set (typically 1-3). Reference-quantized comparison:
// q = fl(fl(zn+ek) - fl(2*dot)), lowest-index tie-break.
// ============================================================
__global__ __launch_bounds__(256, 4)
void rescore_kernel(const float* __restrict__ z, const float* __restrict__ cb,
                    float* __restrict__ out_idx) {
    __shared__ float zs[8][260];
    const int tid = threadIdx.x, w = tid >> 5, lane = tid & 31;
    const int n0 = blockIdx.x * 8;
    const int b = n0 >> 10, hw0 = n0 & 1023;   // 8 | 1024: same b for block
    const float* zb = z + (size_t)b * (D_ * HW_) + hw0;
    #pragma unroll
    for (int i = tid; i < 2048; i += 256) {
        int c = i >> 3, ho = i & 7;
        zs[ho][c] = zb[(size_t)c * HW_ + ho];
    }
    __syncthreads();

    const int n = n0 + w;
    const float zn = g_znorm[n];
    float za[4], zc[4];
    #pragma unroll
    for (int j = 0; j < 4; j++) {
        za[j] = zs[w][4 * lane + j];
        zc[j] = zs[w][128 + 4 * lane + j];
    }
    const int cnt = g_candcnt[n];

    float q = 3.4e38f;
    int   ki = 0x7fffffff;
    for (int j = 0; j < cnt; j++) {
        int k = g_cand[n * MAXC + j];
        const float4* cr = (const float4*)(cb + (size_t)k * D_);
        float4 c0 = cr[lane];
        float4 c1 = cr[32 + lane];
        float p;
        p = za[0] * c0.x;
        p = fmaf(za[1], c0.y, p);
        p = fmaf(za[2], c0.z, p);
        p = fmaf(za[3], c0.w, p);
        p = fmaf(zc[0], c1.x, p);
        p = fmaf(zc[1], c1.y, p);
        p = fmaf(zc[2], c1.z, p);
        p = fmaf(zc[3], c1.w, p);
        #pragma unroll
        for (int off = 16; off > 0; off >>= 1)
            p += __shfl_xor_sync(0xffffffffu, p, off);
        float r = __fadd_rn(zn, g_cbnorm[k]);   // fl(zn + ek)
        float s = fmaf(-2.f, p, r);             // fl(r - 2*dot)
        if (s < q || (s == q && k < ki)) { q = s; ki = k; }
    }
    if (lane == 0) {
        g_idx[n] = ki;
        out_idx[n] = (float)ki;
    }
}

// ============================================================
// gather z_q with exact STE emulation fl(zp + fl(q - zp)) +
// per-block partial sums of (q - zp)^2
// ============================================================
__global__ void gather_loss(const float* __restrict__ z,
                            const float* __restrict__ cb,
                            float* __restrict__ out_zq) {
    __shared__ float red[256];
    int i = blockIdx.x * 256 + threadIdx.x;
    int hw = i & 1023;
    int c  = (i >> 10) & 255;
    int b  = i >> 18;
    int n  = (b << 10) + hw;
    int k  = g_idx[n];
    float q  = cb[(size_t)k * D_ + c];
    float zv = z[i];
    out_zq[i] = __fadd_rn(zv, __fsub_rn(q, zv));
    float d = q - zv;
    red[threadIdx.x] = d * d;
    __syncthreads();
    #pragma unroll
    for (int off = 128; off > 0; off >>= 1) {
        if (threadIdx.x < off) red[threadIdx.x] += red[threadIdx.x + off];
        __syncthreads();
    }
    if (threadIdx.x == 0) g_partial[blockIdx.x] = red[0];
}

__global__ void finalize_loss(float* __restrict__ out_loss) {
    __shared__ double red[1024];
    double s = 0.0;
    for (int i = threadIdx.x; i < ZQ_ELEMS / 256; i += 1024)
        s += (double)g_partial[i];
    red[threadIdx.x] = s;
    __syncthreads();
    #pragma unroll
    for (int off = 512; off > 0; off >>= 1) {
        if (threadIdx.x < off) red[threadIdx.x] += red[threadIdx.x + off];
        __syncthreads();
    }
    if (threadIdx.x == 0)
        out_loss[0] = (float)(1.25 * red[0] / (double)ZQ_ELEMS);
}

// ============================================================
extern "C" void kernel_launch(void* const* d_in, const int* in_sizes, int n_in,
                              void* d_out, int out_size) {
    const float* z  = (const float*)d_in[0];
    const float* cb = (const float*)d_in[1];
    float* out      = (float*)d_out;

    float* out_zq   = out;
    float* out_loss = out + ZQ_ELEMS;
    float* out_idx  = out + ZQ_ELEMS + 1;

    cudaFuncSetAttribute(vq_mma_kernel,
                         cudaFuncAttributeMaxDynamicSharedMemorySize, SM_TOTAL);

    znorm_kernel<<<N_TOT / 256, 256>>>(z);                      // #1
    cb_prep_kernel<<<K_TOT / 8, 256>>>(cb);                     // #2
    cvt_z_kernel<<<dim3(D_ / 32, HW_ / 32, 16), dim3(32, 8)>>>(z); // #3

    vq_mma_kernel<<<N_TOT / 128, 512, SM_TOTAL>>>();            // #4 (profiled)

    rescore_kernel<<<N_TOT / 8, 256>>>(z, cb, out_idx);         // #5

    gather_loss<<<ZQ_ELEMS / 256, 256>>>(z, cb, out_zq);        // #6

    finalize_loss<<<1, 1024>>>(out_loss);                       // #7
}

// round 10
// speedup vs baseline: 1.0660x; 1.0660x over previous
#include <cuda_runtime.h>
#include <cuda_bf16.h>
#include <cstdint>

// Problem constants
#define D_    256
#define HW_   1024            // 32*32
#define N_TOT 16384           // 16 * 1024 vectors
#define K_TOT 8192            // codebook entries
#define ZQ_ELEMS 4194304      // 16*256*32*32
#define NTILES 64             // K_TOT / 128 codes per tile
#define SLACK  4e-4f          // compaction threshold above approx min (bf16)
#define MAXC   32             // max candidates per vector after compaction

// ---- device scratch (no allocations allowed) ----
__device__ float g_cbnorm[K_TOT];
__device__ float g_znorm[N_TOT];
__device__ int   g_idx[N_TOT];
__device__ float g_partial[ZQ_ELEMS / 256];
__device__ __nv_bfloat16 g_zbf16[N_TOT * D_];    // [n][d] row-major (512B rows)
__device__ __nv_bfloat16 g_cbbf16[K_TOT * D_];   // [k][d] row-major (512B rows)
__device__ int   g_cand[N_TOT * MAXC];           // compacted candidates
__device__ int   g_candcnt[N_TOT];               // candidate counts

// ---- smem layout for the MMA kernel (dynamic) ----
#define SM_A   0               // 128 rows x 512B (z tile, resident)
#define SM_B   65536           // 2 x 128 rows x 512B (codebook, dbl buf)
#define SM_NK  196608          // 2 x 128 floats (code norms, dbl buf)
#define SM_TOTAL 197632

// ---- PTX helpers (non-'a' target instructions only) ----
__device__ __forceinline__ uint32_t smem_u32(const void* p) {
    uint32_t a;
    asm("{ .reg .u64 t; cvta.to.shared.u64 t, %1; cvt.u32.u64 %0, t; }"
        : "=r"(a) : "l"(p));
    return a;
}
__device__ __forceinline__ void cp_async16(uint32_t dst, const void* src) {
    asm volatile("cp.async.cg.shared.global [%0], [%1], 16;"
                 :: "r"(dst), "l"(src) : "memory");
}
#define CP_COMMIT() asm volatile("cp.async.commit_group;" ::: "memory")
#define CP_WAIT1()  asm volatile("cp.async.wait_group 1;" ::: "memory")
#define CP_WAIT0()  asm volatile("cp.async.wait_group 0;" ::: "memory")

#define LDSM4(r0, r1, r2, r3, addr)                                        \
    asm volatile("ldmatrix.sync.aligned.m8n8.x4.shared.b16 "               \
                 "{%0,%1,%2,%3}, [%4];"                                    \
                 : "=r"(r0), "=r"(r1), "=r"(r2), "=r"(r3) : "r"(addr))

#define MMA16816(d, a, b0, b1)                                             \
    asm volatile("mma.sync.aligned.m16n8k16.row.col.f32.bf16.bf16.f32 "    \
                 "{%0,%1,%2,%3}, {%4,%5,%6,%7}, {%8,%9}, {%0,%1,%2,%3};"   \
                 : "+f"((d)[0]), "+f"((d)[1]), "+f"((d)[2]), "+f"((d)[3])  \
                 : "r"((a)[0]), "r"((a)[1]), "r"((a)[2]), "r"((a)[3]),     \
                   "r"(b0), "r"(b1))

// branchless top-3 min-chain update with a packed (score|local) u32
#define UPD3(CH, pval, loc) do {                                           \
    uint32_t _u = (__float_as_uint(pval) & 0xFFFFFF00u) | (loc);           \
    uint32_t _t1 = max(_u, (CH)[0]); (CH)[0] = min(_u, (CH)[0]);           \
    uint32_t _t2 = max(_t1, (CH)[1]); (CH)[1] = min(_t1, (CH)[1]);         \
    (CH)[2] = min(_t2, (CH)[2]);                                           \
} while (0)

// ============================================================
// prep: z squared norms per vector (launch #1)
// ============================================================
__global__ void znorm_kernel(const float* __restrict__ z) {
    int n = blockIdx.x * 256 + threadIdx.x;
    int b  = n >> 10;
    int hw = n & 1023;
    const float* p = z + (size_t)b * (D_ * HW_) + hw;
    double s = 0.0;
    #pragma unroll 8
    for (int c = 0; c < D_; c++) {
        float v = p[(size_t)c * HW_];
        s += (double)v * v;
    }
    g_znorm[n] = (float)s;
}

// ============================================================
// prep: fused codebook norms (fp64) + fp32->bf16 convert (launch #2)
// ============================================================
__global__ void cb_prep_kernel(const float* __restrict__ cb) {
    int warp = threadIdx.x >> 5;
    int lane = threadIdx.x & 31;
    int k = blockIdx.x * 8 + warp;
    const float4* row = (const float4*)(cb + (size_t)k * D_);
    float4 v0 = row[lane * 2];
    float4 v1 = row[lane * 2 + 1];
    double s = (double)v0.x * v0.x + (double)v0.y * v0.y
             + (double)v0.z * v0.z + (double)v0.w * v0.w
             + (double)v1.x * v1.x + (double)v1.y * v1.y
             + (double)v1.z * v1.z + (double)v1.w * v1.w;
    #pragma unroll
    for (int off = 16; off > 0; off >>= 1)
        s += __shfl_xor_sync(0xffffffffu, s, off);
    if (lane == 0) g_cbnorm[k] = (float)s;
    __nv_bfloat162 a = __floats2bfloat162_rn(v0.x, v0.y);
    __nv_bfloat162 b = __floats2bfloat162_rn(v0.z, v0.w);
    __nv_bfloat162 c = __floats2bfloat162_rn(v1.x, v1.y);
    __nv_bfloat162 d = __floats2bfloat162_rn(v1.z, v1.w);
    uint4 o;
    o.x = *(const uint32_t*)&a; o.y = *(const uint32_t*)&b;
    o.z = *(const uint32_t*)&c; o.w = *(const uint32_t*)&d;
    *(uint4*)(g_cbbf16 + (size_t)k * D_ + lane * 8) = o;
}

// ============================================================
// prep: z [b,c,hw] fp32 -> g_zbf16 [n][c] bf16 (transpose) (launch #3)
// ============================================================
__global__ void cvt_z_kernel(const float* __restrict__ z) {
    __shared__ float t[32][33];
    int b  = blockIdx.z;
    int hw0 = blockIdx.y * 32;
    int c0  = blockIdx.x * 32;
    int tx = threadIdx.x, ty = threadIdx.y;   // 32 x 8
    #pragma unroll
    for (int r = 0; r < 4; r++) {
        int c = c0 + ty + r * 8;
        t[ty + r * 8][tx] = z[((size_t)b * D_ + c) * HW_ + hw0 + tx];
    }
    __syncthreads();
    #pragma unroll
    for (int r = 0; r < 4; r++) {
        int n = b * HW_ + hw0 + ty + r * 8;
        g_zbf16[(size_t)n * D_ + c0 + tx] = __float2bfloat16_rn(t[tx][ty + r * 8]);
    }
}

// ============================================================
// main: bf16 mma.sync candidate GEMM (launch #4 -> ncu profiles this).
// grid = 128 CTAs (128 z-rows each), 512 threads (16 warps, 4m x 4n).
// Warp tile 32(m) x 32(n); per thread 2 m16 x 4 n8 tiles, 32 accums.
// Epilogue: PAIR-min (2 adjacent columns) packed branchless top-3 per
// chain; loc = t*4 + nt. Compaction expands each in-threshold pair to
// its 2 codes; cap 16 pairs (same count scale as the 0-flip R7 cap).
// ============================================================
__global__ __launch_bounds__(512, 1) void vq_mma_kernel() {
    extern __shared__ __align__(128) char smem[];
    const uint32_t sb = smem_u32(smem);
    const int tid  = threadIdx.x;
    const int lane = tid & 31;
    const int wid  = tid >> 5;
    const int wm   = wid & 3;      // warp row group (0..3), 32 rows each
    const int wn   = wid >> 2;     // warp col group (0..3), 32 cols each
    const int n0   = blockIdx.x * 128;

    // ---- load A (z rows) into smem, swizzled: 4096 chunks, 8/thread ----
    {
        const char* srcA = (const char*)g_zbf16 + (size_t)n0 * 512;
        #pragma unroll
        for (int j = 0; j < 8; j++) {
            int i = tid + j * 512;
            int r = i >> 5, c16 = i & 31;
            uint32_t kb = c16 * 16;
            cp_async16(sb + SM_A + r * 512 + (kb ^ ((r & 7) << 4)),
                       srcA + (size_t)r * 512 + kb);
        }
    }
    // ---- load B tile 0 + norms ----
    {
        const char* srcB = (const char*)g_cbbf16;
        #pragma unroll
        for (int j = 0; j < 8; j++) {
            int i = tid + j * 512;
            int r = i >> 5, c16 = i & 31;
            uint32_t kb = c16 * 16;
            cp_async16(sb + SM_B + r * 512 + (kb ^ ((r & 7) << 4)),
                       srcB + (size_t)r * 512 + kb);
        }
        if (tid < 32)
            cp_async16(sb + SM_NK + tid * 16, (const char*)g_cbnorm + tid * 16);
    }
    CP_COMMIT();

    // ldmatrix lane addressing
    const int lrow8 = ((lane >> 3) & 1) * 8 + (lane & 7);
    const uint32_t kext = (lane >> 4) * 16;
    const uint32_t xorv = (uint32_t)(lane & 7) << 4;
    uint32_t aBase[2];
    #pragma unroll
    for (int mt = 0; mt < 2; mt++)
        aBase[mt] = sb + SM_A + (wm * 32 + mt * 16 + lrow8) * 512;
    uint32_t bOff[2];
    #pragma unroll
    for (int np = 0; np < 2; np++)
        bOff[np] = (wn * 32 + np * 16 + lrow8) * 512;

    // packed top-3 chains: [ (mt*2+rowgroup)*2 + half ][3]
    uint32_t ch[8][3];
    #pragma unroll
    for (int l = 0; l < 8; l++)
        #pragma unroll
        for (int j = 0; j < 3; j++) ch[l][j] = 0xFFFFFFFFu;

    for (int t = 0; t < NTILES; t++) {
        const int buf = t & 1;
        if (t + 1 < NTILES) {
            const char* srcB = (const char*)g_cbbf16 + (size_t)(t + 1) * 128 * 512;
            uint32_t dst = sb + SM_B + (buf ^ 1) * 65536;
            #pragma unroll
            for (int j = 0; j < 8; j++) {
                int i = tid + j * 512;
                int r = i >> 5, c16 = i & 31;
                uint32_t kb = c16 * 16;
                cp_async16(dst + r * 512 + (kb ^ ((r & 7) << 4)),
                           srcB + (size_t)r * 512 + kb);
            }
            if (tid < 32)
                cp_async16(sb + SM_NK + (buf ^ 1) * 512 + tid * 16,
                           (const char*)(g_cbnorm + (t + 1) * 128) + tid * 16);
            CP_COMMIT();
            CP_WAIT1();
        } else {
            CP_WAIT0();
        }
        __syncthreads();

        // ---- 16 k-steps of mma over D=256 ----
        float acc[2][4][4];
        #pragma unroll
        for (int mt = 0; mt < 2; mt++)
            #pragma unroll
            for (int nt = 0; nt < 4; nt++)
                #pragma unroll
                for (int q = 0; q < 4; q++) acc[mt][nt][q] = 0.f;

        const uint32_t bBase = sb + SM_B + buf * 65536;
        #pragma unroll
        for (int ks = 0; ks < 16; ks++) {
            const uint32_t kb = ks * 32;
            uint32_t a[2][4];
            #pragma unroll
            for (int mt = 0; mt < 2; mt++)
                LDSM4(a[mt][0], a[mt][1], a[mt][2], a[mt][3],
                      aBase[mt] + ((kb + kext) ^ xorv));
            uint32_t b[2][4];
            #pragma unroll
            for (int np = 0; np < 2; np++)
                LDSM4(b[np][0], b[np][1], b[np][2], b[np][3],
                      bBase + bOff[np] + ((kb + kext) ^ xorv));
            #pragma unroll
            for (int mt = 0; mt < 2; mt++)
                #pragma unroll
                for (int nt = 0; nt < 4; nt++)
                    MMA16816(acc[mt][nt], a[mt],
                             b[nt >> 1][nt & 1], b[nt >> 1][2 + (nt & 1)]);
        }

        // ---- epilogue: pair-min (2 columns) packed top-3 updates ----
        {
            const float* nk = (const float*)(smem + SM_NK + buf * 512);
            const int cb0 = wn * 32 + 2 * (lane & 3);
            const uint32_t tb4 = (uint32_t)t * 4;
            #pragma unroll
            for (int nt = 0; nt < 4; nt++) {
                int c = cb0 + nt * 8;
                float nkp0 = fmaf(nk[c],     16.f, 2.f);
                float nkp1 = fmaf(nk[c + 1], 16.f, 2.f);
                const int half = nt >> 1;
                const uint32_t loc = tb4 + (uint32_t)nt;   // decode: t=loc>>2, nt=loc&3
                #pragma unroll
                for (int mt = 0; mt < 2; mt++) {
                    #pragma unroll
                    for (int rg = 0; rg < 2; rg++) {
                        float p0 = fmaf(acc[mt][nt][rg * 2 + 0], -32.f, nkp0);
                        float p1 = fmaf(acc[mt][nt][rg * 2 + 1], -32.f, nkp1);
                        UPD3(ch[(mt * 2 + rg) * 2 + half], fminf(p0, p1), loc);
                    }
                }
            }
        }
        __syncthreads();   // safe to overwrite buf next iter
    }

    // ---- dump (score, pair base k) to smem table: [128 rows][32 dom][3] ----
    {
        uint32_t* tabS = (uint32_t*)smem;            // 48KB
        int*      tabK = (int*)(smem + 49152);       // 48KB
        const int colb = wn * 32 + 2 * (lane & 3);
        #pragma unroll
        for (int mt = 0; mt < 2; mt++)
            #pragma unroll
            for (int rg = 0; rg < 2; rg++) {
                int r = wm * 32 + mt * 16 + rg * 8 + (lane >> 2);
                #pragma unroll
                for (int half = 0; half < 2; half++) {
                    int dom = wn * 4 + (lane & 3) + half * 16;
                    const uint32_t* c3 = ch[(mt * 2 + rg) * 2 + half];
                    #pragma unroll
                    for (int j = 0; j < 3; j++) {
                        uint32_t e = c3[j];
                        uint32_t loc = e & 255u;
                        int kb = (int)(loc >> 2) * 128 + (int)(loc & 3u) * 8 + colb;
                        tabS[r * 96 + dom * 3 + j] = e & 0xFFFFFF00u;
                        tabK[r * 96 + dom * 3 + j] = kb;   // pair: kb, kb+1
                    }
                }
            }
    }
    __syncthreads();

    // ---- threshold compaction with pair expansion: 1 thread/row ----
    if (tid < 128) {
        const uint32_t* es = (const uint32_t*)smem + tid * 96;
        const int*      ek = (const int*)(smem + 49152) + tid * 96;
        uint32_t mn = es[0];
        #pragma unroll 8
        for (int i = 1; i < 96; i++) mn = min(mn, es[i]);
        float thr = __uint_as_float(mn) + SLACK * 16.f;   // packed scale
        int cnt = 0;
        int n = n0 + tid;
        #pragma unroll 4
        for (int i = 0; i < 96; i++) {
            if (__uint_as_float(es[i]) <= thr && cnt <= MAXC - 2) {
                int kb = ek[i];
                g_cand[n * MAXC + cnt + 0] = kb;
                g_cand[n * MAXC + cnt + 1] = kb + 1;
                cnt += 2;
            }
        }
        g_candcnt[n] = cnt;
    }
}

// ============================================================
// exact rescore, warp-cooperative over the compacted candidate
// set. Reference-quantized comparison:
// q = fl(fl(zn+ek) - fl(2*dot)), lowest-index tie-break.
// ============================================================
__global__ __launch_bounds__(256, 4)
void rescore_kernel(const float* __restrict__ z, const float* __restrict__ cb,
                    float* __restrict__ out_idx) {
    __shared__ float zs[8][260];
    const int tid = threadIdx.x, w = tid >> 5, lane = tid & 31;
    const int n0 = blockIdx.x * 8;
    const int b = n0 >> 10, hw0 = n0 & 1023;   // 8 | 1024: same b for block
    const float* zb = z + (size_t)b * (D_ * HW_) + hw0;
    #pragma unroll
    for (int i = tid; i < 2048; i += 256) {
        int c = i >> 3, ho = i & 7;
        zs[ho][c] = zb[(size_t)c * HW_ + ho];
    }
    __syncthreads();

    const int n = n0 + w;
    const float zn = g_znorm[n];
    float za[4], zc[4];
    #pragma unroll
    for (int j = 0; j < 4; j++) {
        za[j] = zs[w][4 * lane + j];
        zc[j] = zs[w][128 + 4 * lane + j];
    }
    const int cnt = g_candcnt[n];

    float q = 3.4e38f;
    int   ki = 0x7fffffff;
    for (int j = 0; j < cnt; j++) {
        int k = g_cand[n * MAXC + j];
        const float4* cr = (const float4*)(cb + (size_t)k * D_);
        float4 c0 = cr[lane];
        float4 c1 = cr[32 + lane];
        float p;
        p = za[0] * c0.x;
        p = fmaf(za[1], c0.y, p);
        p = fmaf(za[2], c0.z, p);
        p = fmaf(za[3], c0.w, p);
        p = fmaf(zc[0], c1.x, p);
        p = fmaf(zc[1], c1.y, p);
        p = fmaf(zc[2], c1.z, p);
        p = fmaf(zc[3], c1.w, p);
        #pragma unroll
        for (int off = 16; off > 0; off >>= 1)
            p += __shfl_xor_sync(0xffffffffu, p, off);
        float r = __fadd_rn(zn, g_cbnorm[k]);   // fl(zn + ek)
        float s = fmaf(-2.f, p, r);             // fl(r - 2*dot)
        if (s < q || (s == q && k < ki)) { q = s; ki = k; }
    }
    if (lane == 0) {
        g_idx[n] = ki;
        out_idx[n] = (float)ki;
    }
}

// ============================================================
// gather z_q with exact STE emulation fl(zp + fl(q - zp)) +
// per-block partial sums of (q - zp)^2
// ============================================================
__global__ void gather_loss(const float* __restrict__ z,
                            const float* __restrict__ cb,
                            float* __restrict__ out_zq) {
    __shared__ float red[256];
    int i = blockIdx.x * 256 + threadIdx.x;
    int hw = i & 1023;
    int c  = (i >> 10) & 255;
    int b  = i >> 18;
    int n  = (b << 10) + hw;
    int k  = g_idx[n];
    float q  = cb[(size_t)k * D_ + c];
    float zv = z[i];
    out_zq[i] = __fadd_rn(zv, __fsub_rn(q, zv));
    float d = q - zv;
    red[threadIdx.x] = d * d;
    __syncthreads();
    #pragma unroll
    for (int off = 128; off > 0; off >>= 1) {
        if (threadIdx.x < off) red[threadIdx.x] += red[threadIdx.x + off];
        __syncthreads();
    }
    if (threadIdx.x == 0) g_partial[blockIdx.x] = red[0];
}

__global__ void finalize_loss(float* __restrict__ out_loss) {
    __shared__ double red[1024];
    double s = 0.0;
    for (int i = threadIdx.x; i < ZQ_ELEMS / 256; i += 1024)
        s += (double)g_partial[i];
    red[threadIdx.x] = s;
    __syncthreads();
    #pragma unroll
    for (int off = 512; off > 0; off >>= 1) {
        if (threadIdx.x < off) red[threadIdx.x] += red[threadIdx.x + off];
        __syncthreads();
    }
    if (threadIdx.x == 0)
        out_loss[0] = (float)(1.25 * red[0] / (double)ZQ_ELEMS);
}

// ============================================================
extern "C" void kernel_launch(void* const* d_in, const int* in_sizes, int n_in,
                              void* d_out, int out_size) {
    const float* z  = (const float*)d_in[0];
    const float* cb = (const float*)d_in[1];
    float* out      = (float*)d_out;

    float* out_zq   = out;
    float* out_loss = out + ZQ_ELEMS;
    float* out_idx  = out + ZQ_ELEMS + 1;

    cudaFuncSetAttribute(vq_mma_kernel,
                         cudaFuncAttributeMaxDynamicSharedMemorySize, SM_TOTAL);

    znorm_kernel<<<N_TOT / 256, 256>>>(z);                      // #1
    cb_prep_kernel<<<K_TOT / 8, 256>>>(cb);                     // #2
    cvt_z_kernel<<<dim3(D_ / 32, HW_ / 32, 16), dim3(32, 8)>>>(z); // #3

    vq_mma_kernel<<<N_TOT / 128, 512, SM_TOTAL>>>();            // #4 (profiled)

    rescore_kernel<<<N_TOT / 8, 256>>>(z, cb, out_idx);         // #5

    gather_loss<<<ZQ_ELEMS / 256, 256>>>(z, cb, out_zq);        // #6

    finalize_loss<<<1, 1024>>>(out_loss);                       // #7
}

// round 11
// speedup vs baseline: 1.1716x; 1.0991x over previous
#include <cuda_runtime.h>
#include <cuda_bf16.h>
#include <cstdint>

// Problem constants
#define D_    256
#define HW_   1024            // 32*32
#define N_TOT 16384           // 16 * 1024 vectors
#define K_TOT 8192            // codebook entries
#define ZQ_ELEMS 4194304      // 16*256*32*32
#define NTILES 64             // K_TOT / 128 codes per tile
#define SLACK  4e-4f          // compaction threshold above approx min (bf16)
#define MAXC   32             // max candidates per vector after compaction

// ---- device scratch (no allocations allowed) ----
__device__ float g_cbnorm[K_TOT];
__device__ float g_znorm[N_TOT];
__device__ int   g_idx[N_TOT];
__device__ float g_partial[4096];                // gather block partials
__device__ __nv_bfloat16 g_zbf16[N_TOT * D_];    // [n][d] row-major (512B rows)
__device__ __nv_bfloat16 g_cbbf16[K_TOT * D_];   // [k][d] row-major (512B rows)
__device__ int   g_cand[N_TOT * MAXC];           // compacted candidates
__device__ int   g_candcnt[N_TOT];               // candidate counts

// ---- smem layout for the MMA kernel (dynamic) ----
#define SM_A   0               // 128 rows x 512B (z tile, resident)
#define SM_B   65536           // 2 x 128 rows x 512B (codebook, dbl buf)
#define SM_NK  196608          // 2 x 128 floats (code norms, dbl buf)
#define SM_TOTAL 197632

// ---- PTX helpers (non-'a' target instructions only) ----
__device__ __forceinline__ uint32_t smem_u32(const void* p) {
    uint32_t a;
    asm("{ .reg .u64 t; cvta.to.shared.u64 t, %1; cvt.u32.u64 %0, t; }"
        : "=r"(a) : "l"(p));
    return a;
}
__device__ __forceinline__ void cp_async16(uint32_t dst, const void* src) {
    asm volatile("cp.async.cg.shared.global [%0], [%1], 16;"
                 :: "r"(dst), "l"(src) : "memory");
}
#define CP_COMMIT() asm volatile("cp.async.commit_group;" ::: "memory")
#define CP_WAIT1()  asm volatile("cp.async.wait_group 1;" ::: "memory")
#define CP_WAIT0()  asm volatile("cp.async.wait_group 0;" ::: "memory")

#define LDSM4(r0, r1, r2, r3, addr)                                        \
    asm volatile("ldmatrix.sync.aligned.m8n8.x4.shared.b16 "               \
                 "{%0,%1,%2,%3}, [%4];"                                    \
                 : "=r"(r0), "=r"(r1), "=r"(r2), "=r"(r3) : "r"(addr))

#define MMA16816(d, a, b0, b1)                                             \
    asm volatile("mma.sync.aligned.m16n8k16.row.col.f32.bf16.bf16.f32 "    \
                 "{%0,%1,%2,%3}, {%4,%5,%6,%7}, {%8,%9}, {%0,%1,%2,%3};"   \
                 : "+f"((d)[0]), "+f"((d)[1]), "+f"((d)[2]), "+f"((d)[3])  \
                 : "r"((a)[0]), "r"((a)[1]), "r"((a)[2]), "r"((a)[3]),     \
                   "r"(b0), "r"(b1))

// branchless top-3 min-chain update with a packed (score|local) u32
#define UPD3(CH, pval, loc) do {                                           \
    uint32_t _u = (__float_as_uint(pval) & 0xFFFFFF00u) | (loc);           \
    uint32_t _t1 = max(_u, (CH)[0]); (CH)[0] = min(_u, (CH)[0]);           \
    uint32_t _t2 = max(_t1, (CH)[1]); (CH)[1] = min(_t1, (CH)[1]);         \
    (CH)[2] = min(_t2, (CH)[2]);                                           \
} while (0)

// ============================================================
// prep: z squared norms per vector (launch #1)
// ============================================================
__global__ void znorm_kernel(const float* __restrict__ z) {
    int n = blockIdx.x * 256 + threadIdx.x;
    int b  = n >> 10;
    int hw = n & 1023;
    const float* p = z + (size_t)b * (D_ * HW_) + hw;
    double s = 0.0;
    #pragma unroll 8
    for (int c = 0; c < D_; c++) {
        float v = p[(size_t)c * HW_];
        s += (double)v * v;
    }
    g_znorm[n] = (float)s;
}

// ============================================================
// prep: fused codebook norms (fp64) + fp32->bf16 convert (launch #2)
// ============================================================
__global__ void cb_prep_kernel(const float* __restrict__ cb) {
    int warp = threadIdx.x >> 5;
    int lane = threadIdx.x & 31;
    int k = blockIdx.x * 8 + warp;
    const float4* row = (const float4*)(cb + (size_t)k * D_);
    float4 v0 = row[lane * 2];
    float4 v1 = row[lane * 2 + 1];
    double s = (double)v0.x * v0.x + (double)v0.y * v0.y
             + (double)v0.z * v0.z + (double)v0.w * v0.w
             + (double)v1.x * v1.x + (double)v1.y * v1.y
             + (double)v1.z * v1.z + (double)v1.w * v1.w;
    #pragma unroll
    for (int off = 16; off > 0; off >>= 1)
        s += __shfl_xor_sync(0xffffffffu, s, off);
    if (lane == 0) g_cbnorm[k] = (float)s;
    __nv_bfloat162 a = __floats2bfloat162_rn(v0.x, v0.y);
    __nv_bfloat162 b = __floats2bfloat162_rn(v0.z, v0.w);
    __nv_bfloat162 c = __floats2bfloat162_rn(v1.x, v1.y);
    __nv_bfloat162 d = __floats2bfloat162_rn(v1.z, v1.w);
    uint4 o;
    o.x = *(const uint32_t*)&a; o.y = *(const uint32_t*)&b;
    o.z = *(const uint32_t*)&c; o.w = *(const uint32_t*)&d;
    *(uint4*)(g_cbbf16 + (size_t)k * D_ + lane * 8) = o;
}

// ============================================================
// prep: z [b,c,hw] fp32 -> g_zbf16 [n][c] bf16 (transpose) (launch #3)
// ============================================================
__global__ void cvt_z_kernel(const float* __restrict__ z) {
    __shared__ float t[32][33];
    int b  = blockIdx.z;
    int hw0 = blockIdx.y * 32;
    int c0  = blockIdx.x * 32;
    int tx = threadIdx.x, ty = threadIdx.y;   // 32 x 8
    #pragma unroll
    for (int r = 0; r < 4; r++) {
        int c = c0 + ty + r * 8;
        t[ty + r * 8][tx] = z[((size_t)b * D_ + c) * HW_ + hw0 + tx];
    }
    __syncthreads();
    #pragma unroll
    for (int r = 0; r < 4; r++) {
        int n = b * HW_ + hw0 + ty + r * 8;
        g_zbf16[(size_t)n * D_ + c0 + tx] = __float2bfloat16_rn(t[tx][ty + r * 8]);
    }
}

// ============================================================
// main: bf16 mma.sync candidate GEMM (launch #4 -> ncu profiles this).
// grid = 128 CTAs (128 z-rows each), 512 threads (16 warps, 4m x 4n).
// Warp tile 32(m) x 32(n); per thread 2 m16 x 4 n8 tiles, 32 accums.
// Epilogue: PAIR-min (2 adjacent columns) packed branchless top-3 per
// chain; loc = t*4 + nt. Compaction expands each in-threshold pair to
// its 2 codes; cap 16 pairs (proven 0-flip scale).
// ============================================================
__global__ __launch_bounds__(512, 1) void vq_mma_kernel() {
    extern __shared__ __align__(128) char smem[];
    const uint32_t sb = smem_u32(smem);
    const int tid  = threadIdx.x;
    const int lane = tid & 31;
    const int wid  = tid >> 5;
    const int wm   = wid & 3;      // warp row group (0..3), 32 rows each
    const int wn   = wid >> 2;     // warp col group (0..3), 32 cols each
    const int n0   = blockIdx.x * 128;

    // ---- load A (z rows) into smem, swizzled: 4096 chunks, 8/thread ----
    {
        const char* srcA = (const char*)g_zbf16 + (size_t)n0 * 512;
        #pragma unroll
        for (int j = 0; j < 8; j++) {
            int i = tid + j * 512;
            int r = i >> 5, c16 = i & 31;
            uint32_t kb = c16 * 16;
            cp_async16(sb + SM_A + r * 512 + (kb ^ ((r & 7) << 4)),
                       srcA + (size_t)r * 512 + kb);
        }
    }
    // ---- load B tile 0 + norms ----
    {
        const char* srcB = (const char*)g_cbbf16;
        #pragma unroll
        for (int j = 0; j < 8; j++) {
            int i = tid + j * 512;
            int r = i >> 5, c16 = i & 31;
            uint32_t kb = c16 * 16;
            cp_async16(sb + SM_B + r * 512 + (kb ^ ((r & 7) << 4)),
                       srcB + (size_t)r * 512 + kb);
        }
        if (tid < 32)
            cp_async16(sb + SM_NK + tid * 16, (const char*)g_cbnorm + tid * 16);
    }
    CP_COMMIT();

    // ldmatrix lane addressing
    const int lrow8 = ((lane >> 3) & 1) * 8 + (lane & 7);
    const uint32_t kext = (lane >> 4) * 16;
    const uint32_t xorv = (uint32_t)(lane & 7) << 4;
    uint32_t aBase[2];
    #pragma unroll
    for (int mt = 0; mt < 2; mt++)
        aBase[mt] = sb + SM_A + (wm * 32 + mt * 16 + lrow8) * 512;
    uint32_t bOff[2];
    #pragma unroll
    for (int np = 0; np < 2; np++)
        bOff[np] = (wn * 32 + np * 16 + lrow8) * 512;

    // packed top-3 chains: [ (mt*2+rowgroup)*2 + half ][3]
    uint32_t ch[8][3];
    #pragma unroll
    for (int l = 0; l < 8; l++)
        #pragma unroll
        for (int j = 0; j < 3; j++) ch[l][j] = 0xFFFFFFFFu;

    for (int t = 0; t < NTILES; t++) {
        const int buf = t & 1;
        if (t + 1 < NTILES) {
            const char* srcB = (const char*)g_cbbf16 + (size_t)(t + 1) * 128 * 512;
            uint32_t dst = sb + SM_B + (buf ^ 1) * 65536;
            #pragma unroll
            for (int j = 0; j < 8; j++) {
                int i = tid + j * 512;
                int r = i >> 5, c16 = i & 31;
                uint32_t kb = c16 * 16;
                cp_async16(dst + r * 512 + (kb ^ ((r & 7) << 4)),
                           srcB + (size_t)r * 512 + kb);
            }
            if (tid < 32)
                cp_async16(sb + SM_NK + (buf ^ 1) * 512 + tid * 16,
                           (const char*)(g_cbnorm + (t + 1) * 128) + tid * 16);
            CP_COMMIT();
            CP_WAIT1();
        } else {
            CP_WAIT0();
        }
        __syncthreads();

        // ---- 16 k-steps of mma over D=256 ----
        float acc[2][4][4];
        #pragma unroll
        for (int mt = 0; mt < 2; mt++)
            #pragma unroll
            for (int nt = 0; nt < 4; nt++)
                #pragma unroll
                for (int q = 0; q < 4; q++) acc[mt][nt][q] = 0.f;

        const uint32_t bBase = sb + SM_B + buf * 65536;
        #pragma unroll
        for (int ks = 0; ks < 16; ks++) {
            const uint32_t kb = ks * 32;
            uint32_t a[2][4];
            #pragma unroll
            for (int mt = 0; mt < 2; mt++)
                LDSM4(a[mt][0], a[mt][1], a[mt][2], a[mt][3],
                      aBase[mt] + ((kb + kext) ^ xorv));
            uint32_t b[2][4];
            #pragma unroll
            for (int np = 0; np < 2; np++)
                LDSM4(b[np][0], b[np][1], b[np][2], b[np][3],
                      bBase + bOff[np] + ((kb + kext) ^ xorv));
            #pragma unroll
            for (int mt = 0; mt < 2; mt++)
                #pragma unroll
                for (int nt = 0; nt < 4; nt++)
                    MMA16816(acc[mt][nt], a[mt],
                             b[nt >> 1][nt & 1], b[nt >> 1][2 + (nt & 1)]);
        }

        // ---- epilogue: pair-min (2 columns) packed top-3 updates ----
        {
            const float* nk = (const float*)(smem + SM_NK + buf * 512);
            const int cb0 = wn * 32 + 2 * (lane & 3);
            const uint32_t tb4 = (uint32_t)t * 4;
            #pragma unroll
            for (int nt = 0; nt < 4; nt++) {
                int c = cb0 + nt * 8;
                float nkp0 = fmaf(nk[c],     16.f, 2.f);
                float nkp1 = fmaf(nk[c + 1], 16.f, 2.f);
                const int half = nt >> 1;
                const uint32_t loc = tb4 + (uint32_t)nt;   // decode: t=loc>>2, nt=loc&3
                #pragma unroll
                for (int mt = 0; mt < 2; mt++) {
                    #pragma unroll
                    for (int rg = 0; rg < 2; rg++) {
                        float p0 = fmaf(acc[mt][nt][rg * 2 + 0], -32.f, nkp0);
                        float p1 = fmaf(acc[mt][nt][rg * 2 + 1], -32.f, nkp1);
                        UPD3(ch[(mt * 2 + rg) * 2 + half], fminf(p0, p1), loc);
                    }
                }
            }
        }
        __syncthreads();   // safe to overwrite buf next iter
    }

    // ---- dump (score, pair base k) to smem table: [128 rows][32 dom][3] ----
    {
        uint32_t* tabS = (uint32_t*)smem;            // 48KB
        int*      tabK = (int*)(smem + 49152);       // 48KB
        const int colb = wn * 32 + 2 * (lane & 3);
        #pragma unroll
        for (int mt = 0; mt < 2; mt++)
            #pragma unroll
            for (int rg = 0; rg < 2; rg++) {
                int r = wm * 32 + mt * 16 + rg * 8 + (lane >> 2);
                #pragma unroll
                for (int half = 0; half < 2; half++) {
                    int dom = wn * 4 + (lane & 3) + half * 16;
                    const uint32_t* c3 = ch[(mt * 2 + rg) * 2 + half];
                    #pragma unroll
                    for (int j = 0; j < 3; j++) {
                        uint32_t e = c3[j];
                        uint32_t loc = e & 255u;
                        int kb = (int)(loc >> 2) * 128 + (int)(loc & 3u) * 8 + colb;
                        tabS[r * 96 + dom * 3 + j] = e & 0xFFFFFF00u;
                        tabK[r * 96 + dom * 3 + j] = kb;   // pair: kb, kb+1
                    }
                }
            }
    }
    __syncthreads();

    // ---- threshold compaction with pair expansion: 1 thread/row ----
    if (tid < 128) {
        const uint32_t* es = (const uint32_t*)smem + tid * 96;
        const int*      ek = (const int*)(smem + 49152) + tid * 96;
        uint32_t mn = es[0];
        #pragma unroll 8
        for (int i = 1; i < 96; i++) mn = min(mn, es[i]);
        float thr = __uint_as_float(mn) + SLACK * 16.f;   // packed scale
        int cnt = 0;
        int n = n0 + tid;
        #pragma unroll 4
        for (int i = 0; i < 96; i++) {
            if (__uint_as_float(es[i]) <= thr && cnt <= MAXC - 2) {
                int kb = ek[i];
                g_cand[n * MAXC + cnt + 0] = kb;
                g_cand[n * MAXC + cnt + 1] = kb + 1;
                cnt += 2;
            }
        }
        g_candcnt[n] = cnt;
    }
}

// ============================================================
// exact rescore, warp-cooperative over the compacted candidate
// set. Reference-quantized comparison:
// q = fl(fl(zn+ek) - fl(2*dot)), lowest-index tie-break.
// ============================================================
__global__ __launch_bounds__(256, 4)
void rescore_kernel(const float* __restrict__ z, const float* __restrict__ cb,
                    float* __restrict__ out_idx) {
    __shared__ float zs[8][260];
    const int tid = threadIdx.x, w = tid >> 5, lane = tid & 31;
    const int n0 = blockIdx.x * 8;
    const int b = n0 >> 10, hw0 = n0 & 1023;   // 8 | 1024: same b for block
    const float* zb = z + (size_t)b * (D_ * HW_) + hw0;
    #pragma unroll
    for (int i = tid; i < 2048; i += 256) {
        int c = i >> 3, ho = i & 7;
        zs[ho][c] = zb[(size_t)c * HW_ + ho];
    }
    __syncthreads();

    const int n = n0 + w;
    const float zn = g_znorm[n];
    float za[4], zc[4];
    #pragma unroll
    for (int j = 0; j < 4; j++) {
        za[j] = zs[w][4 * lane + j];
        zc[j] = zs[w][128 + 4 * lane + j];
    }
    const int cnt = g_candcnt[n];

    float q = 3.4e38f;
    int   ki = 0x7fffffff;
    for (int j = 0; j < cnt; j++) {
        int k = g_cand[n * MAXC + j];
        const float4* cr = (const float4*)(cb + (size_t)k * D_);
        float4 c0 = cr[lane];
        float4 c1 = cr[32 + lane];
        float p;
        p = za[0] * c0.x;
        p = fmaf(za[1], c0.y, p);
        p = fmaf(za[2], c0.z, p);
        p = fmaf(za[3], c0.w, p);
        p = fmaf(zc[0], c1.x, p);
        p = fmaf(zc[1], c1.y, p);
        p = fmaf(zc[2], c1.z, p);
        p = fmaf(zc[3], c1.w, p);
        #pragma unroll
        for (int off = 16; off > 0; off >>= 1)
            p += __shfl_xor_sync(0xffffffffu, p, off);
        float r = __fadd_rn(zn, g_cbnorm[k]);   // fl(zn + ek)
        float s = fmaf(-2.f, p, r);             // fl(r - 2*dot)
        if (s < q || (s == q && k < ki)) { q = s; ki = k; }
    }
    if (lane == 0) {
        g_idx[n] = ki;
        out_idx[n] = (float)ki;
    }
}

// ============================================================
// gather z_q with exact STE emulation fl(zp + fl(q - zp)),
// TRANSPOSE-TILED so codebook reads are coalesced (1 line/warp-load
// instead of 32). Block = 32 c x 32 hw tile of one batch.
// grid = (8, 32, 16), 256 threads.
// ============================================================
__global__ void gather_loss(const float* __restrict__ z,
                            const float* __restrict__ cb,
                            float* __restrict__ out_zq) {
    __shared__ float q[32][33];
    __shared__ float red[256];
    const int c0  = blockIdx.x * 32;
    const int hw0 = blockIdx.y * 32;
    const int b   = blockIdx.z;
    const int tid = threadIdx.x;
    const int lane = tid & 31, grp = tid >> 5;   // 8 warps

    // phase 1: q[n_local][c_local] <- cb[idx[n]][c0+lane]  (coalesced)
    #pragma unroll
    for (int it = 0; it < 4; it++) {
        int nl = grp + it * 8;
        int k = g_idx[b * HW_ + hw0 + nl];
        q[nl][lane] = cb[(size_t)k * D_ + c0 + lane];
    }
    __syncthreads();

    // phase 2: lanes along hw (coalesced z read / zq write)
    float acc = 0.f;
    #pragma unroll
    for (int it = 0; it < 4; it++) {
        int cy = grp + it * 8;                   // c_local
        size_t idx = ((size_t)(b * D_ + c0 + cy)) * HW_ + hw0 + lane;
        float zv = z[idx];
        float qv = q[lane][cy];                  // transposed, conflict-free
        out_zq[idx] = __fadd_rn(zv, __fsub_rn(qv, zv));
        float d = qv - zv;
        acc = fmaf(d, d, acc);
    }
    red[tid] = acc;
    __syncthreads();
    #pragma unroll
    for (int off = 128; off > 0; off >>= 1) {
        if (tid < off) red[tid] += red[tid + off];
        __syncthreads();
    }
    if (tid == 0)
        g_partial[(b * 32 + blockIdx.y) * 8 + blockIdx.x] = red[0];
}

__global__ void finalize_loss(float* __restrict__ out_loss) {
    __shared__ double red[1024];
    double s = 0.0;
    for (int i = threadIdx.x; i < 4096; i += 1024)
        s += (double)g_partial[i];
    red[threadIdx.x] = s;
    __syncthreads();
    #pragma unroll
    for (int off = 512; off > 0; off >>= 1) {
        if (threadIdx.x < off) red[threadIdx.x] += red[threadIdx.x + off];
        __syncthreads();
    }
    if (threadIdx.x == 0)
        out_loss[0] = (float)(1.25 * red[0] / (double)ZQ_ELEMS);
}

// ============================================================
extern "C" void kernel_launch(void* const* d_in, const int* in_sizes, int n_in,
                              void* d_out, int out_size) {
    const float* z  = (const float*)d_in[0];
    const float* cb = (const float*)d_in[1];
    float* out      = (float*)d_out;

    float* out_zq   = out;
    float* out_loss = out + ZQ_ELEMS;
    float* out_idx  = out + ZQ_ELEMS + 1;

    cudaFuncSetAttribute(vq_mma_kernel,
                         cudaFuncAttributeMaxDynamicSharedMemorySize, SM_TOTAL);

    znorm_kernel<<<N_TOT / 256, 256>>>(z);                      // #1
    cb_prep_kernel<<<K_TOT / 8, 256>>>(cb);                     // #2
    cvt_z_kernel<<<dim3(D_ / 32, HW_ / 32, 16), dim3(32, 8)>>>(z); // #3

    vq_mma_kernel<<<N_TOT / 128, 512, SM_TOTAL>>>();            // #4 (profiled)

    rescore_kernel<<<N_TOT / 8, 256>>>(z, cb, out_idx);         // #5

    gather_loss<<<dim3(D_ / 32, HW_ / 32, 16), 256>>>(z, cb, out_zq); // #6

    finalize_loss<<<1, 1024>>>(out_loss);                       // #7
}